// round 10
// baseline (speedup 1.0000x reference)
#include <cuda_runtime.h>
#include <cstdint>
#include <math.h>

// Problem constants
#define S_DIM 256
#define CH    32          // head dim
#define NH    8           // heads
#define CIN   128         // input channels
#define CQK   256         // NH*CH
#define NROWS (S_DIM * S_DIM)

typedef unsigned long long ull;

// ---------------------------------------------------------------------------
// Packed f32x2 helpers (sm_103a FFMA2 path — PTX-only)
// ---------------------------------------------------------------------------
__device__ __forceinline__ ull pk2(float lo, float hi) {
    ull r; asm("mov.b64 %0, {%1, %2};" : "=l"(r) : "f"(lo), "f"(hi)); return r;
}
__device__ __forceinline__ float2 upk2(ull v) {
    float lo, hi; asm("mov.b64 {%0, %1}, %2;" : "=f"(lo), "=f"(hi) : "l"(v));
    return make_float2(lo, hi);
}
__device__ __forceinline__ ull fma2(ull a, ull b, ull c) {
    ull d; asm("fma.rn.f32x2 %0, %1, %2, %3;" : "=l"(d) : "l"(a), "l"(b), "l"(c)); return d;
}

// ---------------------------------------------------------------------------
// Scratch
// ---------------------------------------------------------------------------
__device__ float g_Q[(size_t)NROWS * CQK];
__device__ float g_K[(size_t)NROWS * CQK];
__device__ float g_V[(size_t)NROWS * CQK];
__device__ float g_G[(size_t)NROWS * CQK];
__device__ float g_O[(size_t)NROWS * CQK];
__device__ int   g_mask_code;   // 0=int32, 1=uint8, 2=float32

// ---------------------------------------------------------------------------
// Mask dtype detection
// ---------------------------------------------------------------------------
__global__ void detect_mask_kernel(const unsigned char* __restrict__ m, int nbytes)
{
    __shared__ int f_float, f_u8;
    if (threadIdx.x == 0) { f_float = 0; f_u8 = 0; }
    __syncthreads();
    int lf = 0, lu = 0;
    for (int i = threadIdx.x; i < nbytes; i += blockDim.x) {
        unsigned char v = m[i];
        if (v >= 2) lf = 1;
        if ((i & 3) && v) lu = 1;
    }
    if (lf) atomicOr(&f_float, 1);
    if (lu) atomicOr(&f_u8, 1);
    __syncthreads();
    if (threadIdx.x == 0)
        g_mask_code = f_float ? 2 : (f_u8 ? 1 : 0);
}

// ---------------------------------------------------------------------------
// fp32 SGEMM v6: 128x128 tile, BK=16 (half the barriers of BK=8),
// 256 threads, FFMA2 2x2 blocks of 4x4 microtile (conflict-free B loads),
// double-buffered smem (32KB).
//   mode 0: none / 1: C*=scale / 2: sigmoid(C+evec) / 3: C+evec
// ---------------------------------------------------------------------------
#define GBM 128
#define GBN 128
#define GBK 16

__global__ __launch_bounds__(256, 2)
void sgemm6(const float* __restrict__ A, const float* __restrict__ B,
            float* __restrict__ C, int M, int N, int K,
            int mode, const float* __restrict__ evec, float scale)
{
    __shared__ float As[2][GBK * GBM];   // [k][m]
    __shared__ float Bs[2][GBK * GBN];   // [k][n]

    const int t  = threadIdx.x;
    const int bm = blockIdx.y * GBM;
    const int bn = blockIdx.x * GBN;

    // A loader: 128 rows x 16 k; 2 threads/row, 2 float4 each
    const int arow = t >> 1;
    const int ak   = (t & 1) * 8;
    // B loader: 16 rows x 128 cols; 2 float4 each
    const int brow = t >> 4;
    const int bcol = (t & 15) * 8;

    const int tx = t & 15;
    const int ty = t >> 4;

    ull acc2[8][4];
#pragma unroll
    for (int i = 0; i < 8; i++)
#pragma unroll
        for (int j = 0; j < 4; j++) acc2[i][j] = 0ULL;

    {
        const float* arp = A + (size_t)(bm + arow) * K + ak;
        float4 a0 = *(const float4*)arp;
        float4 a1 = *(const float4*)(arp + 4);
        As[0][(ak + 0) * GBM + arow] = a0.x;
        As[0][(ak + 1) * GBM + arow] = a0.y;
        As[0][(ak + 2) * GBM + arow] = a0.z;
        As[0][(ak + 3) * GBM + arow] = a0.w;
        As[0][(ak + 4) * GBM + arow] = a1.x;
        As[0][(ak + 5) * GBM + arow] = a1.y;
        As[0][(ak + 6) * GBM + arow] = a1.z;
        As[0][(ak + 7) * GBM + arow] = a1.w;
        *(float4*)&Bs[0][brow * GBN + bcol] =
            *(const float4*)(B + (size_t)brow * N + bn + bcol);
        *(float4*)&Bs[0][brow * GBN + bcol + 4] =
            *(const float4*)(B + (size_t)brow * N + bn + bcol + 4);
    }
    __syncthreads();

    int p = 0;
    for (int k0 = 0; k0 < K; k0 += GBK) {
        const bool has_next = (k0 + GBK) < K;
        float4 a0g, a1g, b0g, b1g;
        if (has_next) {
            const float* arp = A + (size_t)(bm + arow) * K + k0 + GBK + ak;
            a0g = *(const float4*)arp;
            a1g = *(const float4*)(arp + 4);
            b0g = *(const float4*)(B + (size_t)(k0 + GBK + brow) * N + bn + bcol);
            b1g = *(const float4*)(B + (size_t)(k0 + GBK + brow) * N + bn + bcol + 4);
        }

        const float* Asp = As[p];
        const float* Bsp = Bs[p];
#pragma unroll
        for (int kk = 0; kk < GBK; kk++) {
            float4 a0 = *(const float4*)&Asp[kk * GBM + ty * 4];        // broadcast
            float4 a1 = *(const float4*)&Asp[kk * GBM + 64 + ty * 4];   // broadcast
            ulonglong2 b0 = *(const ulonglong2*)&Bsp[kk * GBN + tx * 4];      // CF
            ulonglong2 b1 = *(const ulonglong2*)&Bsp[kk * GBN + 64 + tx * 4]; // CF
            ull b2[4] = {b0.x, b0.y, b1.x, b1.y};
            ull aa[8] = {pk2(a0.x, a0.x), pk2(a0.y, a0.y), pk2(a0.z, a0.z), pk2(a0.w, a0.w),
                         pk2(a1.x, a1.x), pk2(a1.y, a1.y), pk2(a1.z, a1.z), pk2(a1.w, a1.w)};
#pragma unroll
            for (int i = 0; i < 8; i++)
#pragma unroll
                for (int j = 0; j < 4; j++)
                    acc2[i][j] = fma2(aa[i], b2[j], acc2[i][j]);
        }

        if (has_next) {
            const int q = p ^ 1;
            As[q][(ak + 0) * GBM + arow] = a0g.x;
            As[q][(ak + 1) * GBM + arow] = a0g.y;
            As[q][(ak + 2) * GBM + arow] = a0g.z;
            As[q][(ak + 3) * GBM + arow] = a0g.w;
            As[q][(ak + 4) * GBM + arow] = a1g.x;
            As[q][(ak + 5) * GBM + arow] = a1g.y;
            As[q][(ak + 6) * GBM + arow] = a1g.z;
            As[q][(ak + 7) * GBM + arow] = a1g.w;
            *(float4*)&Bs[q][brow * GBN + bcol] = b0g;
            *(float4*)&Bs[q][brow * GBN + bcol + 4] = b1g;
            __syncthreads();
            p = q;
        }
    }

#pragma unroll
    for (int i = 0; i < 8; i++) {
        const int row = bm + ((i < 4) ? (ty * 4 + i) : (64 + ty * 4 + i - 4));
        float vlo[4], vhi[4];
        {
            float2 v0 = upk2(acc2[i][0]);
            float2 v1 = upk2(acc2[i][1]);
            vlo[0] = v0.x; vlo[1] = v0.y; vlo[2] = v1.x; vlo[3] = v1.y;
            float2 v2 = upk2(acc2[i][2]);
            float2 v3 = upk2(acc2[i][3]);
            vhi[0] = v2.x; vhi[1] = v2.y; vhi[2] = v3.x; vhi[3] = v3.y;
        }
#pragma unroll
        for (int j = 0; j < 4; j++) {
            const int clo = bn + tx * 4 + j;
            const int chi = bn + 64 + tx * 4 + j;
            float zl = vlo[j], zh = vhi[j];
            if (mode == 1)      { zl *= scale; zh *= scale; }
            else if (mode == 2) {
                zl = 1.f / (1.f + __expf(-(zl + evec[clo])));
                zh = 1.f / (1.f + __expf(-(zh + evec[chi])));
            }
            else if (mode == 3) { zl += evec[clo]; zh += evec[chi]; }
            vlo[j] = zl; vhi[j] = zh;
        }
        *(float4*)(C + (size_t)row * N + bn + tx * 4) =
            make_float4(vlo[0], vlo[1], vlo[2], vlo[3]);
        *(float4*)(C + (size_t)row * N + bn + 64 + tx * 4) =
            make_float4(vhi[0], vhi[1], vhi[2], vhi[3]);
    }
}

// ---------------------------------------------------------------------------
// Attention v6: 512 threads (4 warps/SMSP), fused in-register softmax.
// Block = (h, s, qh): 128 q rows x 256 k.
// Pass1: ONE 8x8 FFMA2 tile per thread (16 warps x 32 lanes = 512 tiles);
//        warp lanes share 8 q rows and cover all 256 k -> shfl softmax.
// Pass2: 2q x 4c per thread.
// ---------------------------------------------------------------------------
#define LSTR 268
#define OFF_KS   34304
#define OFF_QS   42496
#define OFF_VS   46592
#define OFF_ADDM 54784
#define ATTN_SMEM_BYTES (55040 * 4)

__global__ __launch_bounds__(512, 1)
void attn6(const float* __restrict__ Q, const float* __restrict__ Km,
           const float* __restrict__ V, const float* __restrict__ G,
           const float* __restrict__ bias, const void* __restrict__ mask,
           float* __restrict__ O)
{
    extern __shared__ float sm[];
    float* L    = sm;                 // holds normalized P after pass 1
    float* Ks   = sm + OFF_KS;
    float* Qs   = sm + OFF_QS;
    float* Vs   = sm + OFF_VS;
    float* addm = sm + OFF_ADDM;

    const int h  = blockIdx.x;
    const int s  = blockIdx.y;
    const int qh = blockIdx.z;
    const int t  = threadIdx.x;

    // ---- stage Q transposed: Qs[c][q] (4 threads/row, 8 c each) ----
    {
        const int q = t >> 2, c0 = (t & 3) * 8;
        const float4* src = (const float4*)(Q + ((size_t)(s * S_DIM + qh * 128 + q)) * CQK + h * CH + c0);
        float4 v0 = src[0], v1 = src[1];
        Qs[(c0 + 0) * 128 + q] = v0.x; Qs[(c0 + 1) * 128 + q] = v0.y;
        Qs[(c0 + 2) * 128 + q] = v0.z; Qs[(c0 + 3) * 128 + q] = v0.w;
        Qs[(c0 + 4) * 128 + q] = v1.x; Qs[(c0 + 5) * 128 + q] = v1.y;
        Qs[(c0 + 6) * 128 + q] = v1.z; Qs[(c0 + 7) * 128 + q] = v1.w;
    }
    // ---- stage K transposed: Ks[c][k] (2 threads/row, 16 c each) ----
    {
        const int k = t >> 1, c0 = (t & 1) * 16;
        const float4* src = (const float4*)(Km + ((size_t)(s * S_DIM + k)) * CQK + h * CH + c0);
#pragma unroll
        for (int j = 0; j < 4; j++) {
            float4 v = src[j];
            Ks[(c0 + 4 * j + 0) * S_DIM + k] = v.x;
            Ks[(c0 + 4 * j + 1) * S_DIM + k] = v.y;
            Ks[(c0 + 4 * j + 2) * S_DIM + k] = v.z;
            Ks[(c0 + 4 * j + 3) * S_DIM + k] = v.w;
        }
    }
    // ---- stage V natural [k][c] + mask ----
    {
        const float4* Vg4 = (const float4*)V;
        const size_t rowbase = ((size_t)s * S_DIM) * (CQK / 4) + h * (CH / 4);
#pragma unroll
        for (int f = t; f < S_DIM * (CH / 4); f += 512) {
            int k = f >> 3, c4 = f & 7;
            ((float4*)Vs)[k * 8 + c4] = Vg4[rowbase + (size_t)k * (CQK / 4) + c4];
        }
        if (t < 256) {
            const int idx = s * S_DIM + t;
            const int code = g_mask_code;
            bool mv;
            if (code == 2)      mv = ((const float*)mask)[idx] != 0.f;
            else if (code == 1) mv = ((const unsigned char*)mask)[idx] != 0;
            else                mv = ((const int*)mask)[idx] != 0;
            addm[t] = mv ? 0.f : -1e30f;
        }
    }
    __syncthreads();

    // ---- pass 1 + fused softmax: one 8x8 tile per thread ----
    const float* brow = bias + ((size_t)(h * S_DIM + qh * 128)) * S_DIM;
    {
        const int qi = t >> 5, ki = t & 31;   // qi warp-uniform
        const int q0 = qi * 8;
        const int kA = ki * 4, kB = 128 + ki * 4;

        ull acc2[8][4];
#pragma unroll
        for (int i = 0; i < 8; i++)
#pragma unroll
            for (int j = 0; j < 4; j++) acc2[i][j] = 0ULL;

#pragma unroll 2
        for (int c = 0; c < CH; c++) {
            float4 qa = *(const float4*)&Qs[c * 128 + q0];        // broadcast
            float4 qb = *(const float4*)&Qs[c * 128 + q0 + 4];    // broadcast
            ulonglong2 k0v = *(const ulonglong2*)&Ks[c * S_DIM + kA];  // CF
            ulonglong2 k1v = *(const ulonglong2*)&Ks[c * S_DIM + kB];  // CF
            ull b2[4] = {k0v.x, k0v.y, k1v.x, k1v.y};
            ull aa[8] = {pk2(qa.x, qa.x), pk2(qa.y, qa.y), pk2(qa.z, qa.z), pk2(qa.w, qa.w),
                         pk2(qb.x, qb.x), pk2(qb.y, qb.y), pk2(qb.z, qb.z), pk2(qb.w, qb.w)};
#pragma unroll
            for (int i = 0; i < 8; i++)
#pragma unroll
                for (int j = 0; j < 4; j++)
                    acc2[i][j] = fma2(aa[i], b2[j], acc2[i][j]);
        }

        // unpack + bias + mask into v[8][8]
        float v[8][8];
        {
            float4 amA = *(const float4*)&addm[kA];
            float4 amB = *(const float4*)&addm[kB];
#pragma unroll
            for (int i = 0; i < 8; i++) {
                const int q = q0 + i;
                float4 bbA = *(const float4*)(brow + (size_t)q * S_DIM + kA);
                float4 bbB = *(const float4*)(brow + (size_t)q * S_DIM + kB);
                float2 d0 = upk2(acc2[i][0]);
                float2 d1 = upk2(acc2[i][1]);
                float2 d2 = upk2(acc2[i][2]);
                float2 d3 = upk2(acc2[i][3]);
                v[i][0] = d0.x + bbA.x + amA.x;
                v[i][1] = d0.y + bbA.y + amA.y;
                v[i][2] = d1.x + bbA.z + amA.z;
                v[i][3] = d1.y + bbA.w + amA.w;
                v[i][4] = d2.x + bbB.x + amB.x;
                v[i][5] = d2.y + bbB.y + amB.y;
                v[i][6] = d3.x + bbB.z + amB.z;
                v[i][7] = d3.y + bbB.w + amB.w;
            }
        }

        // row max across warp (ILP-8 butterfly)
        float rm[8];
#pragma unroll
        for (int i = 0; i < 8; i++) {
            float m01 = fmaxf(fmaxf(v[i][0], v[i][1]), fmaxf(v[i][2], v[i][3]));
            float m23 = fmaxf(fmaxf(v[i][4], v[i][5]), fmaxf(v[i][6], v[i][7]));
            rm[i] = fmaxf(m01, m23);
        }
#pragma unroll
        for (int st = 16; st >= 1; st >>= 1)
#pragma unroll
            for (int i = 0; i < 8; i++)
                rm[i] = fmaxf(rm[i], __shfl_xor_sync(0xFFFFFFFFu, rm[i], st));

        // exp + row sum across warp
        float rs[8];
#pragma unroll
        for (int i = 0; i < 8; i++) {
            float s0 = 0.f;
#pragma unroll
            for (int j = 0; j < 8; j++) {
                v[i][j] = __expf(v[i][j] - rm[i]);
                s0 += v[i][j];
            }
            rs[i] = s0;
        }
#pragma unroll
        for (int st = 16; st >= 1; st >>= 1)
#pragma unroll
            for (int i = 0; i < 8; i++)
                rs[i] += __shfl_xor_sync(0xFFFFFFFFu, rs[i], st);

        // normalize + store P
#pragma unroll
        for (int i = 0; i < 8; i++) {
            const int q = q0 + i;
            const float riv = 1.f / rs[i];
            *(float4*)&L[q * LSTR + kA] = make_float4(
                v[i][0] * riv, v[i][1] * riv, v[i][2] * riv, v[i][3] * riv);
            *(float4*)&L[q * LSTR + kB] = make_float4(
                v[i][4] * riv, v[i][5] * riv, v[i][6] * riv, v[i][7] * riv);
        }
    }
    __syncthreads();

    // ---- pass 2: O = P.V, 2q x 4c per thread (P pre-normalized) ----
    {
        const int q0 = (t >> 3) * 2;
        const int c0 = (t & 7) * 4;
        ull acc2[2][2];
        acc2[0][0] = acc2[0][1] = acc2[1][0] = acc2[1][1] = 0ULL;

#pragma unroll 4
        for (int k0 = 0; k0 < S_DIM; k0 += 4) {
            ulonglong2 v0 = *(const ulonglong2*)&Vs[(k0 + 0) * CH + c0];
            ulonglong2 v1 = *(const ulonglong2*)&Vs[(k0 + 1) * CH + c0];
            ulonglong2 v2 = *(const ulonglong2*)&Vs[(k0 + 2) * CH + c0];
            ulonglong2 v3 = *(const ulonglong2*)&Vs[(k0 + 3) * CH + c0];
#pragma unroll
            for (int i = 0; i < 2; i++) {
                float4 pv = *(const float4*)&L[(q0 + i) * LSTR + k0];
                ull a0 = pk2(pv.x, pv.x);
                ull a1 = pk2(pv.y, pv.y);
                ull a2 = pk2(pv.z, pv.z);
                ull a3 = pk2(pv.w, pv.w);
                acc2[i][0] = fma2(a0, v0.x, acc2[i][0]);
                acc2[i][1] = fma2(a0, v0.y, acc2[i][1]);
                acc2[i][0] = fma2(a1, v1.x, acc2[i][0]);
                acc2[i][1] = fma2(a1, v1.y, acc2[i][1]);
                acc2[i][0] = fma2(a2, v2.x, acc2[i][0]);
                acc2[i][1] = fma2(a2, v2.y, acc2[i][1]);
                acc2[i][0] = fma2(a3, v3.x, acc2[i][0]);
                acc2[i][1] = fma2(a3, v3.y, acc2[i][1]);
            }
        }
#pragma unroll
        for (int i = 0; i < 2; i++) {
            const int q = q0 + i;
            const size_t row = (size_t)(s * S_DIM + qh * 128 + q);
            float4 gv = *(const float4*)(G + row * CQK + h * CH + c0);
            float2 x0 = upk2(acc2[i][0]);
            float2 x1 = upk2(acc2[i][1]);
            float4 ov;
            ov.x = x0.x * gv.x;
            ov.y = x0.y * gv.y;
            ov.z = x1.x * gv.z;
            ov.w = x1.y * gv.w;
            *(float4*)(O + row * CQK + h * CH + c0) = ov;
        }
    }
}

// ---------------------------------------------------------------------------
// Launch
// ---------------------------------------------------------------------------
extern "C" void kernel_launch(void* const* d_in, const int* in_sizes, int n_in,
                              void* d_out, int out_size)
{
    const float* x    = (const float*)d_in[0];
    const float* bias = (const float*)d_in[1];
    const void*  mask = d_in[2];
    const float* Wq   = (const float*)d_in[3];
    const float* Wk   = (const float*)d_in[4];
    const float* Wv   = (const float*)d_in[5];
    const float* Wo   = (const float*)d_in[6];
    const float* bo   = (const float*)d_in[7];
    const float* Wg   = (const float*)d_in[8];
    const float* bg   = (const float*)d_in[9];
    float* out = (float*)d_out;

    void *pQ, *pK, *pV, *pG, *pO;
    cudaGetSymbolAddress(&pQ, g_Q);
    cudaGetSymbolAddress(&pK, g_K);
    cudaGetSymbolAddress(&pV, g_V);
    cudaGetSymbolAddress(&pG, g_G);
    cudaGetSymbolAddress(&pO, g_O);
    float* Qb = (float*)pQ; float* Kb = (float*)pK; float* Vb = (float*)pV;
    float* Gb = (float*)pG; float* Ob = (float*)pO;

    const float qscale = 0.17677669529663687f;   // 1/sqrt(32)

    dim3 gproj(CQK / GBN, NROWS / GBM);   // (2, 512)
    sgemm6<<<gproj, 256>>>(x, Wq, Qb, NROWS, CQK, CIN, 1, nullptr, qscale);
    sgemm6<<<gproj, 256>>>(x, Wk, Kb, NROWS, CQK, CIN, 0, nullptr, 1.f);
    sgemm6<<<gproj, 256>>>(x, Wv, Vb, NROWS, CQK, CIN, 0, nullptr, 1.f);
    sgemm6<<<gproj, 256>>>(x, Wg, Gb, NROWS, CQK, CIN, 2, bg, 1.f);

    detect_mask_kernel<<<1, 256>>>((const unsigned char*)mask, S_DIM * S_DIM);

    cudaFuncSetAttribute(attn6, cudaFuncAttributeMaxDynamicSharedMemorySize, ATTN_SMEM_BYTES);
    attn6<<<dim3(NH, S_DIM, 2), 512, ATTN_SMEM_BYTES>>>(Qb, Kb, Vb, Gb, bias, mask, Ob);

    dim3 gout(CIN / GBN, NROWS / GBM);    // (1, 512)
    sgemm6<<<gout, 256>>>(Ob, Wo, out, NROWS, CIN, CQK, 3, bo, 1.f);
}